// round 16
// baseline (speedup 1.0000x reference)
#include <cuda_runtime.h>
#include <cuda_bf16.h>
#include <cstdint>

#define NN     10000
#define EE     160000
#define ENTOT  (EE + NN)
#define TT     32
#define INC    128
#define HIDC   64
#define NHEADS 8
#define F1     512        // NHEADS * HID
#define GH     256
#define G3     768        // 3 * GH

// -------- phase-overlapped arenas (disjoint lifetimes; <2GB each) -----------
#define ARENA_A_BYTES ((size_t)TT * NN * 2 * F1 * 4)            // 1,310,720,000
#define ARENA_B_BYTES ((size_t)TT * NN * G3 * 4)                //   983,040,000
#define ARENA_C_REAL  ((size_t)245760000)
__device__ __align__(256) char g_arenaA[ARENA_A_BYTES];
__device__ __align__(256) char g_arenaB[ARENA_B_BYTES];
__device__ __align__(256) char g_arenaC[ARENA_C_REAL];

// ---------------- small persistent scratch ----------------
__device__ float g_degf[NN];
__device__ float g_loopsum[NN * 3];
__device__ int   g_cnt[NN];
__device__ int   g_rowptr[NN + 1];
__device__ int   g_fill[NN];
__device__ int   g_adj_src[ENTOT];
__device__ float g_adj_ea[ENTOT * 3];
__device__ float g_ghF[NN * G3];
__device__ float g_ghB[NN * G3];
__device__ float g_hf[NN * GH];
__device__ float g_hb[NN * GH];
__device__ float g_mean[2 * GH];
__device__ int      g_barc;
__device__ unsigned g_barg;
__device__ __nv_bfloat16 g_w1s [2 * 2 * F1 * INC];
__device__ __nv_bfloat16 g_w2s [2 * 2 * HIDC * F1];
__device__ __nv_bfloat16 g_hfs [2 * NN * GH];
__device__ __nv_bfloat16 g_hbs [2 * NN * GH];
__device__ __nv_bfloat16 g_wihs_f[2 * G3 * HIDC];
__device__ __nv_bfloat16 g_wihs_b[2 * G3 * HIDC];
__device__ __nv_bfloat16 g_whhs_f[2 * G3 * GH];
__device__ __nv_bfloat16 g_whhs_b[2 * G3 * GH];

// ---------------- helpers ----------------
#define SWZ(off) ((off) ^ (((off) >> 3) & 0x70))

__device__ __forceinline__ uint32_t smem_u32(const void* p) {
    uint32_t a;
    asm("{ .reg .u64 t; cvta.to.shared.u64 t, %1; cvt.u32.u64 %0, t; }" : "=r"(a) : "l"(p));
    return a;
}
__device__ __forceinline__ void cp_async16(uint32_t dst, const void* src, int sz) {
    asm volatile("cp.async.ca.shared.global [%0], [%1], 16, %2;"
                 :: "r"(dst), "l"(src), "r"(sz) : "memory");
}
__device__ __forceinline__ void cp_commit() {
    asm volatile("cp.async.commit_group;" ::: "memory");
}
__device__ __forceinline__ void cp_wait1() {
    asm volatile("cp.async.wait_group 1;" ::: "memory");
}
__device__ __forceinline__ void cp_wait0() {
    asm volatile("cp.async.wait_group 0;" ::: "memory");
}
__device__ __forceinline__ void ldsm_x4(uint32_t* r, uint32_t addr) {
    asm volatile("ldmatrix.sync.aligned.m8n8.x4.shared.b16 {%0,%1,%2,%3}, [%4];"
                 : "=r"(r[0]), "=r"(r[1]), "=r"(r[2]), "=r"(r[3]) : "r"(addr));
}
__device__ __forceinline__ void mma_bf16(float* c, const uint32_t* a, uint32_t b0, uint32_t b1) {
    asm volatile("mma.sync.aligned.m16n8k16.row.col.f32.bf16.bf16.f32 "
                 "{%0,%1,%2,%3}, {%4,%5,%6,%7}, {%8,%9}, {%0,%1,%2,%3};"
                 : "+f"(c[0]), "+f"(c[1]), "+f"(c[2]), "+f"(c[3])
                 : "r"(a[0]), "r"(a[1]), "r"(a[2]), "r"(a[3]), "r"(b0), "r"(b1));
}
__device__ __forceinline__ void split_bf16(float v, __nv_bfloat16& hi, __nv_bfloat16& lo) {
    hi = __float2bfloat16_rn(v);
    lo = __float2bfloat16_rn(v - __bfloat162float(hi));
}

// ---- bf16x3 emulated-fp32 GEMM body: C[M,N] = A[M,K] @ BT[N,K]^T ------------
// 2-stage cp.async pipeline, 64KB smem, 2 blocks/SM co-residency.
__device__ __forceinline__ void gemm_body(
    const __nv_bfloat16* __restrict__ Ahi, const __nv_bfloat16* __restrict__ Alo,
    const __nv_bfloat16* __restrict__ Bhi, const __nv_bfloat16* __restrict__ Blo,
    float* __restrict__ C, int M, int N, int K, char* smem, int bm, int bn)
{
    constexpr int TSZ   = 128 * 128;
    constexpr int STAGE = 2 * TSZ;
    const uint32_t sbase = smem_u32(smem);
    const int t = threadIdx.x;
    const int warp = t >> 5, lane = t & 31;
    const int tI = lane >> 3, lr = lane & 7;
    const int wm0 = (warp & 1) * 64;
    const int wn0 = (warp >> 1) * 32;
    const size_t Kb = (size_t)K * 2;

    float acc[4][4][4];
    #pragma unroll
    for (int i = 0; i < 4; i++)
        #pragma unroll
        for (int j = 0; j < 4; j++)
            #pragma unroll
            for (int k = 0; k < 4; k++) acc[i][j][k] = 0.f;

    const int NC = K >> 5;

    auto load_stage = [&](int s, int c) {
        uint32_t sa = sbase + s * STAGE;
        uint32_t sb = sa + TSZ;
        int k0b = c << 6;
        #pragma unroll
        for (int i = 0; i < 4; i++) {
            int idx = t + i * 256;
            int row = idx >> 3, c8 = idx & 7;
            const char* base = (const char*)((c8 & 4) ? Alo : Ahi);
            const char* src = base + (size_t)(bm + row) * Kb + k0b + (c8 & 3) * 16;
            int sz = (bm + row < M) ? 16 : 0;
            cp_async16(sa + SWZ((row << 7) | (c8 << 4)), src, sz);
        }
        #pragma unroll
        for (int i = 0; i < 4; i++) {
            int idx = t + i * 256;
            int row = idx >> 3, c8 = idx & 7;
            const char* base = (const char*)((c8 & 4) ? Blo : Bhi);
            const char* src = base + (size_t)(bn + row) * Kb + k0b + (c8 & 3) * 16;
            cp_async16(sb + SWZ((row << 7) | (c8 << 4)), src, 16);
        }
        cp_commit();
    };

    load_stage(0, 0);

    for (int c = 0; c < NC; c++) {
        if (c + 1 < NC) { load_stage((c + 1) & 1, c + 1); cp_wait1(); }
        else            { cp_wait0(); }
        __syncthreads();

        uint32_t sa = sbase + (c & 1) * STAGE;
        uint32_t sb = sa + TSZ;
        #pragma unroll
        for (int ks = 0; ks < 2; ks++) {
            uint32_t Ah[4][4], Al[4][4], Bh[2][4], Bl[2][4];
            #pragma unroll
            for (int ma = 0; ma < 4; ma++) {
                int row = wm0 + ma * 16 + ((tI & 1) << 3) + lr;
                int kb = (ks << 5) | ((tI >> 1) << 4);
                ldsm_x4(Ah[ma], sa + SWZ((row << 7) | kb));
                ldsm_x4(Al[ma], sa + SWZ((row << 7) | (64 + kb)));
            }
            #pragma unroll
            for (int nb = 0; nb < 2; nb++) {
                int row = wn0 + nb * 16 + ((tI >> 1) << 3) + lr;
                int kb = (ks << 5) | ((tI & 1) << 4);
                ldsm_x4(Bh[nb], sb + SWZ((row << 7) | kb));
                ldsm_x4(Bl[nb], sb + SWZ((row << 7) | (64 + kb)));
            }
            #pragma unroll
            for (int ma = 0; ma < 4; ma++)
                #pragma unroll
                for (int na = 0; na < 4; na++) {
                    int nb = na >> 1, off = (na & 1) * 2;
                    mma_bf16(acc[ma][na], Ah[ma], Bl[nb][off], Bl[nb][off + 1]);
                    mma_bf16(acc[ma][na], Al[ma], Bh[nb][off], Bh[nb][off + 1]);
                    mma_bf16(acc[ma][na], Ah[ma], Bh[nb][off], Bh[nb][off + 1]);
                }
        }
        __syncthreads();
    }

    #pragma unroll
    for (int ma = 0; ma < 4; ma++) {
        int row = bm + wm0 + ma * 16 + (lane >> 2);
        #pragma unroll
        for (int na = 0; na < 4; na++) {
            int col = bn + wn0 + na * 8 + 2 * (lane & 3);
            if (row < M)
                *reinterpret_cast<float2*>(&C[(size_t)row * N + col]) =
                    make_float2(acc[ma][na][0], acc[ma][na][1]);
            if (row + 8 < M)
                *reinterpret_cast<float2*>(&C[(size_t)(row + 8) * N + col]) =
                    make_float2(acc[ma][na][2], acc[ma][na][3]);
        }
    }
}

// ---- single-direction GRU gate body (quad-vectorized), gid = block index ----
__device__ __forceinline__ void gate_body(
    const float* __restrict__ gi, const float* __restrict__ gh,
    const float* __restrict__ bih, const float* __restrict__ bhh,
    float* __restrict__ h, __nv_bfloat16* __restrict__ hp, int gid)
{
    int q = gid * 256 + threadIdx.x;
    if (q >= NN * GH / 4) return;
    int n = q / (GH / 4), j = (q % (GH / 4)) * 4;
    const float* gin = gi + (size_t)n * G3;
    const float* ghn = gh + (size_t)n * G3;
    float4 gr = *(const float4*)(gin + j);
    float4 gz = *(const float4*)(gin + GH + j);
    float4 gn = *(const float4*)(gin + 2 * GH + j);
    float4 hr = *(const float4*)(ghn + j);
    float4 hz = *(const float4*)(ghn + GH + j);
    float4 hn4 = *(const float4*)(ghn + 2 * GH + j);
    float4 br = *(const float4*)(bih + j);
    float4 bz = *(const float4*)(bih + GH + j);
    float4 bn = *(const float4*)(bih + 2 * GH + j);
    float4 cr = *(const float4*)(bhh + j);
    float4 cz = *(const float4*)(bhh + GH + j);
    float4 cn = *(const float4*)(bhh + 2 * GH + j);
    size_t hidx = (size_t)n * GH + j;
    float4 hv = *(const float4*)(h + hidx);
    float4 ho;
    #pragma unroll
    for (int k = 0; k < 4; k++) {
        float grk = (&gr.x)[k] + (&br.x)[k], hrk = (&hr.x)[k] + (&cr.x)[k];
        float gzk = (&gz.x)[k] + (&bz.x)[k], hzk = (&hz.x)[k] + (&cz.x)[k];
        float gnk = (&gn.x)[k] + (&bn.x)[k], hnk = (&hn4.x)[k] + (&cn.x)[k];
        float r = 1.f / (1.f + __expf(-(grk + hrk)));
        float z = 1.f / (1.f + __expf(-(gzk + hzk)));
        float nv = tanhf(gnk + r * hnk);
        (&ho.x)[k] = (1.f - z) * nv + z * (&hv.x)[k];
    }
    *(float4*)(h + hidx) = ho;
    #pragma unroll
    for (int k = 0; k < 4; k++) {
        __nv_bfloat16 hi, lo;
        split_bf16((&ho.x)[k], hi, lo);
        hp[hidx + k] = hi;
        hp[NN * GH + hidx + k] = lo;
    }
}

__global__ void __launch_bounds__(256, 2) tgemm(
    const __nv_bfloat16* __restrict__ Ahi, const __nv_bfloat16* __restrict__ Alo,
    const __nv_bfloat16* __restrict__ Bhi, const __nv_bfloat16* __restrict__ Blo,
    float* __restrict__ C, int M, int N, int K)
{
    extern __shared__ char smem[];
    gemm_body(Ahi, Alo, Bhi, Blo, C, M, N, K, smem, blockIdx.y * 128, blockIdx.x * 128);
}

__global__ void __launch_bounds__(256, 2) tgemm_b2(
    const __nv_bfloat16* Ahi0, const __nv_bfloat16* Alo0,
    const __nv_bfloat16* Bhi0, const __nv_bfloat16* Blo0, float* C0,
    const __nv_bfloat16* Ahi1, const __nv_bfloat16* Alo1,
    const __nv_bfloat16* Bhi1, const __nv_bfloat16* Blo1, float* C1,
    int M, int N, int K)
{
    extern __shared__ char smem[];
    if (blockIdx.z == 0) gemm_body(Ahi0, Alo0, Bhi0, Blo0, C0, M, N, K, smem,
                                   blockIdx.y * 128, blockIdx.x * 128);
    else                 gemm_body(Ahi1, Alo1, Bhi1, Blo1, C1, M, N, K, smem,
                                   blockIdx.y * 128, blockIdx.x * 128);
}

// ---- persistent GRU chain: one launch, software grid barrier ----------------
#define NBGEMM (6 * 79)        // (G3/128) * ceil(NN/128) = 474
#define NBGATE 2500            // NN*GH/4 / 256
#define NPERS  296             // 2 blocks/SM * 148 SMs (<= co-residency)

__device__ __forceinline__ void grid_bar(unsigned* gen) {
    __syncthreads();
    if (threadIdx.x == 0) {
        unsigned g = *gen;
        __threadfence();
        if (atomicAdd(&g_barc, 1) == NPERS - 1) {
            atomicExch(&g_barc, 0);
            __threadfence();
            atomicExch(&g_barg, g + 1);
        } else {
            while (atomicAdd(&g_barg, 0u) < g + 1) {}
        }
        __threadfence();
    }
    __syncthreads();
    *gen += 1;
}

__global__ void __launch_bounds__(256, 2) chain_persist(
    __nv_bfloat16* hfs, __nv_bfloat16* hbs,
    const __nv_bfloat16* whhF, const __nv_bfloat16* whhB,
    float* ghF, float* ghB,
    const float* giF, const float* giB,
    const float* bihf, const float* bhhf,
    const float* bihb, const float* bhhb,
    float* hf, float* hb)
{
    extern __shared__ char smem[];
    const size_t WHHPL = (size_t)G3 * GH;
    unsigned gen = 0;
    for (int t = 0; t < TT; t++) {
        // Phase A: GEMM_F(t) + gate_B(t-1)
        for (int it = blockIdx.x; it < NBGEMM + NBGATE; it += NPERS) {
            if (it < NBGEMM) {
                int bx = it % (G3 / 128), by = it / (G3 / 128);
                gemm_body(hfs, hfs + NN * GH, whhF, whhF + WHHPL, ghF,
                          NN, G3, GH, smem, by * 128, bx * 128);
            } else if (t > 0) {
                gate_body(giB + (size_t)(TT - t) * NN * G3, ghB, bihb, bhhb,
                          hb, hbs, it - NBGEMM);
            }
        }
        grid_bar(&gen);
        // Phase B: GEMM_B(t) + gate_F(t)
        for (int it = blockIdx.x; it < NBGEMM + NBGATE; it += NPERS) {
            if (it < NBGEMM) {
                int bx = it % (G3 / 128), by = it / (G3 / 128);
                gemm_body(hbs, hbs + NN * GH, whhB, whhB + WHHPL, ghB,
                          NN, G3, GH, smem, by * 128, bx * 128);
            } else {
                gate_body(giF + (size_t)t * NN * G3, ghF, bihf, bhhf,
                          hf, hfs, it - NBGEMM);
            }
        }
        grid_bar(&gen);
    }
    // final gate_B (step TT-1 -> gi index 0)
    for (int it = blockIdx.x; it < NBGATE; it += NPERS)
        gate_body(giB, ghB, bihb, bhhb, hb, hbs, it);
}

// ------------- transpose + split ---------------------------------------------
__global__ void k_transpose_split(const float* __restrict__ in, __nv_bfloat16* __restrict__ out,
                                  int R, int Ccols, size_t plane) {
    __shared__ float tile[32][33];
    int c0 = blockIdx.x * 32, r0 = blockIdx.y * 32;
    int x = threadIdx.x, y = threadIdx.y;
    for (int j = 0; j < 32; j += 8) {
        int r = r0 + y + j, c = c0 + x;
        if (r < R && c < Ccols) tile[y + j][x] = in[(size_t)r * Ccols + c];
    }
    __syncthreads();
    for (int j = 0; j < 32; j += 8) {
        int c = c0 + y + j, r = r0 + x;
        if (c < Ccols && r < R) {
            __nv_bfloat16 hi, lo;
            split_bf16(tile[x][y + j], hi, lo);
            out[(size_t)c * R + r] = hi;
            out[plane + (size_t)c * R + r] = lo;
        }
    }
}

__global__ void k_split(const float* __restrict__ in, __nv_bfloat16* __restrict__ out, size_t n) {
    size_t i = (size_t)blockIdx.x * blockDim.x + threadIdx.x;
    if (i >= n) return;
    __nv_bfloat16 hi, lo;
    split_bf16(in[i], hi, lo);
    out[i] = hi;
    out[n + i] = lo;
}

// ---------------- init (fused zeros) ----------------
__global__ void k_init(float* degf, float* loopsum, int* cnt, int* fill) {
    int i = blockIdx.x * blockDim.x + threadIdx.x;
    if (i < NN) { degf[i] = 0.f; cnt[i] = 0; fill[i] = 0; }
    if (i < 3 * NN) loopsum[i] = 0.f;
}

// ---------------- CSR precompute ----------------
__global__ void k_count(const float* __restrict__ ea, const int* __restrict__ dst,
                        float* degf, float* loopsum, int* cnt) {
    int e = blockIdx.x * blockDim.x + threadIdx.x;
    if (e >= EE) return;
    int d = dst[e];
    atomicAdd(&degf[d], 1.f);
    atomicAdd(&cnt[d], 1);
    atomicAdd(&loopsum[d * 3 + 0], ea[e * 3 + 0]);
    atomicAdd(&loopsum[d * 3 + 1], ea[e * 3 + 1]);
    atomicAdd(&loopsum[d * 3 + 2], ea[e * 3 + 2]);
}

__global__ void k_scan(const int* __restrict__ cnt, int* __restrict__ rowptr) {
    __shared__ int tmp[1024];
    __shared__ int carry_s;
    int tid = threadIdx.x;
    if (tid == 0) { carry_s = 0; rowptr[0] = 0; }
    __syncthreads();
    for (int base = 0; base < NN; base += 1024) {
        int i = base + tid;
        int v = (i < NN) ? (cnt[i] + 1) : 0;
        tmp[tid] = v;
        __syncthreads();
        #pragma unroll
        for (int off = 1; off < 1024; off <<= 1) {
            int tv = (tid >= off) ? tmp[tid - off] : 0;
            __syncthreads();
            tmp[tid] += tv;
            __syncthreads();
        }
        if (i < NN) rowptr[i + 1] = carry_s + tmp[tid];
        __syncthreads();
        if (tid == 0) carry_s += tmp[1023];
        __syncthreads();
    }
}

__global__ void k_scatter_e(const float* __restrict__ ea, const int* __restrict__ src,
                            const int* __restrict__ dst, const int* __restrict__ rowptr,
                            int* fill, int* adj_src, float* adj_ea) {
    int e = blockIdx.x * blockDim.x + threadIdx.x;
    if (e >= EE) return;
    int d = dst[e];
    int pos = rowptr[d] + atomicAdd(&fill[d], 1);
    adj_src[pos] = src[e];
    adj_ea[pos * 3 + 0] = ea[e * 3 + 0];
    adj_ea[pos * 3 + 1] = ea[e * 3 + 1];
    adj_ea[pos * 3 + 2] = ea[e * 3 + 2];
}

__global__ void k_scatter_loop(const float* __restrict__ degf, const float* __restrict__ loopsum,
                               const int* __restrict__ rowptr, int* fill,
                               int* adj_src, float* adj_ea) {
    int n = blockIdx.x * blockDim.x + threadIdx.x;
    if (n >= NN) return;
    int pos = rowptr[n] + atomicAdd(&fill[n], 1);
    adj_src[pos] = n;
    float dm = fmaxf(degf[n], 1.f);
    adj_ea[pos * 3 + 0] = loopsum[n * 3 + 0] / dm;
    adj_ea[pos * 3 + 1] = loopsum[n * 3 + 1] / dm;
    adj_ea[pos * 3 + 2] = loopsum[n * 3 + 2] / dm;
}

// ---- GAT1 edge kernel: 2-edge-unrolled online softmax, warp == head --------
__global__ void __launch_bounds__(256) gat_edge1(
    const float* __restrict__ xlr,
    const float* __restrict__ we, const float* __restrict__ att,
    const float* __restrict__ bias,
    const int* __restrict__ rowptr, const int* __restrict__ adj_src,
    const float* __restrict__ adj_ea,
    __nv_bfloat16* __restrict__ outp)
{
    constexpr size_t H1PL = (size_t)TT * NN * F1;
    int n = blockIdx.x, tc = blockIdx.y;
    int warp = threadIdx.x >> 5, lane = threadIdx.x & 31;
    int c0 = warp * 64 + lane, c1 = c0 + 32;
    const float* base = xlr + (size_t)tc * NN * (2 * F1);
    const float* xrrow = base + (size_t)n * (2 * F1) + F1;
    float xr0 = xrrow[c0], xr1 = xrrow[c1];
    float a0 = att[c0], a1 = att[c1];
    float w00 = we[c0], w01 = we[F1 + c0], w02 = we[2 * F1 + c0];
    float w10 = we[c1], w11 = we[F1 + c1], w12 = we[2 * F1 + c1];
    int beg = rowptr[n], end = rowptr[n + 1];
    float m_run = -1e30f, s_run = 0.f, acc0 = 0.f, acc1 = 0.f;

    for (int p = beg; p < end; p += 2) {
        bool has2 = (p + 1 < end);
        int sa = adj_src[p];
        int sb = has2 ? adj_src[p + 1] : sa;
        float ea0 = adj_ea[3 * p + 0], ea1 = adj_ea[3 * p + 1], ea2 = adj_ea[3 * p + 2];
        float eb0 = 0.f, eb1 = 0.f, eb2 = 0.f;
        if (has2) { eb0 = adj_ea[3 * p + 3]; eb1 = adj_ea[3 * p + 4]; eb2 = adj_ea[3 * p + 5]; }
        const float* ra = base + (size_t)sa * (2 * F1);
        const float* rb = base + (size_t)sb * (2 * F1);
        float xa0 = __ldg(&ra[c0]), xa1 = __ldg(&ra[c1]);
        float xb0 = __ldg(&rb[c0]), xb1 = __ldg(&rb[c1]);
        float ma0 = xa0 + xr0 + ea0 * w00 + ea1 * w01 + ea2 * w02;
        float ma1 = xa1 + xr1 + ea0 * w10 + ea1 * w11 + ea2 * w12;
        float mb0 = xb0 + xr0 + eb0 * w00 + eb1 * w01 + eb2 * w02;
        float mb1 = xb1 + xr1 + eb0 * w10 + eb1 * w11 + eb2 * w12;
        ma0 = (ma0 > 0.f) ? ma0 : 0.2f * ma0;
        ma1 = (ma1 > 0.f) ? ma1 : 0.2f * ma1;
        mb0 = (mb0 > 0.f) ? mb0 : 0.2f * mb0;
        mb1 = (mb1 > 0.f) ? mb1 : 0.2f * mb1;
        float pa = ma0 * a0 + ma1 * a1;
        float pb = mb0 * a0 + mb1 * a1;
        #pragma unroll
        for (int o = 16; o; o >>= 1) {
            pa += __shfl_xor_sync(0xffffffffu, pa, o);
            pb += __shfl_xor_sync(0xffffffffu, pb, o);
        }
        float pm = has2 ? fmaxf(pa, pb) : pa;
        float newm = fmaxf(m_run, pm);
        float sc = __expf(m_run - newm);
        float wa = __expf(pa - newm);
        float wb = has2 ? __expf(pb - newm) : 0.f;
        s_run = s_run * sc + wa + wb;
        acc0 = acc0 * sc + wa * xa0 + wb * xb0;
        acc1 = acc1 * sc + wa * xa1 + wb * xb1;
        m_run = newm;
    }
    float inv = 1.f / s_run;
    float o0 = acc0 * inv + bias[c0];
    float o1 = acc1 * inv + bias[c1];
    o0 = (o0 > 0.f) ? o0 : (__expf(o0) - 1.f);
    o1 = (o1 > 0.f) ? o1 : (__expf(o1) - 1.f);
    size_t orow = ((size_t)tc * NN + n) * F1;
    __nv_bfloat16 hi, lo;
    split_bf16(o0, hi, lo); outp[orow + c0] = hi; outp[H1PL + orow + c0] = lo;
    split_bf16(o1, hi, lo); outp[orow + c1] = hi; outp[H1PL + orow + c1] = lo;
}

// ---- GAT2 edge kernel: 2-edge-unrolled, warp == node (1 head) --------------
__global__ void __launch_bounds__(256) gat_edge2(
    const float* __restrict__ xlr,
    const float* __restrict__ we, const float* __restrict__ att,
    const float* __restrict__ bias,
    const int* __restrict__ rowptr, const int* __restrict__ adj_src,
    const float* __restrict__ adj_ea,
    __nv_bfloat16* __restrict__ outp)
{
    constexpr size_t EMBPL = (size_t)TT * NN * HIDC;
    int warp = threadIdx.x >> 5, lane = threadIdx.x & 31;
    int n = blockIdx.x * 8 + warp, tc = blockIdx.y;
    int c0 = lane, c1 = lane + 32;
    const float* base = xlr + (size_t)tc * NN * (2 * HIDC);
    const float* xrrow = base + (size_t)n * (2 * HIDC) + HIDC;
    float xr0 = xrrow[c0], xr1 = xrrow[c1];
    float a0 = att[c0], a1 = att[c1];
    float w00 = we[c0], w01 = we[HIDC + c0], w02 = we[2 * HIDC + c0];
    float w10 = we[c1], w11 = we[HIDC + c1], w12 = we[2 * HIDC + c1];
    int beg = rowptr[n], end = rowptr[n + 1];
    float m_run = -1e30f, s_run = 0.f, acc0 = 0.f, acc1 = 0.f;

    for (int p = beg; p < end; p += 2) {
        bool has2 = (p + 1 < end);
        int sa = adj_src[p];
        int sb = has2 ? adj_src[p + 1] : sa;
        float ea0 = adj_ea[3 * p + 0], ea1 = adj_ea[3 * p + 1], ea2 = adj_ea[3 * p + 2];
        float eb0 = 0.f, eb1 = 0.f, eb2 = 0.f;
        if (has2) { eb0 = adj_ea[3 * p + 3]; eb1 = adj_ea[3 * p + 4]; eb2 = adj_ea[3 * p + 5]; }
        const float* ra = base + (size_t)sa * (2 * HIDC);
        const float* rb = base + (size_t)sb * (2 * HIDC);
        float xa0 = __ldg(&ra[c0]), xa1 = __ldg(&ra[c1]);
        float xb0 = __ldg(&rb[c0]), xb1 = __ldg(&rb[c1]);
        float ma0 = xa0 + xr0 + ea0 * w00 + ea1 * w01 + ea2 * w02;
        float ma1 = xa1 + xr1 + ea0 * w10 + ea1 * w11 + ea2 * w12;
        float mb0 = xb0 + xr0 + eb0 * w00 + eb1 * w01 + eb2 * w02;
        float mb1 = xb1 + xr1 + eb0 * w10 + eb1 * w11 + eb2 * w12;
        ma0 = (ma0 > 0.f) ? ma0 : 0.2f * ma0;
        ma1 = (ma1 > 0.f) ? ma1 : 0.2f * ma1;
        mb0 = (mb0 > 0.f) ? mb0 : 0.2f * mb0;
        mb1 = (mb1 > 0.f) ? mb1 : 0.2f * mb1;
        float pa = ma0 * a0 + ma1 * a1;
        float pb = mb0 * a0 + mb1 * a1;
        #pragma unroll
        for (int o = 16; o; o >>= 1) {
            pa += __shfl_xor_sync(0xffffffffu, pa, o);
            pb += __shfl_xor_sync(0xffffffffu, pb, o);
        }
        float pm = has2 ? fmaxf(pa, pb) : pa;
        float newm = fmaxf(m_run, pm);
        float sc = __expf(m_run - newm);
        float wa = __expf(pa - newm);
        float wb = has2 ? __expf(pb - newm) : 0.f;
        s_run = s_run * sc + wa + wb;
        acc0 = acc0 * sc + wa * xa0 + wb * xb0;
        acc1 = acc1 * sc + wa * xa1 + wb * xb1;
        m_run = newm;
    }
    float inv = 1.f / s_run;
    float o0 = acc0 * inv + bias[c0];
    float o1 = acc1 * inv + bias[c1];
    o0 = (o0 > 0.f) ? o0 : (__expf(o0) - 1.f);
    o1 = (o1 > 0.f) ? o1 : (__expf(o1) - 1.f);
    size_t orow = ((size_t)tc * NN + n) * HIDC;
    __nv_bfloat16 hi, lo;
    split_bf16(o0, hi, lo); outp[orow + c0] = hi; outp[EMBPL + orow + c0] = lo;
    split_bf16(o1, hi, lo); outp[orow + c1] = hi; outp[EMBPL + orow + c1] = lo;
}

__global__ void k_zero_h2(float* hF, float* hB, __nv_bfloat16* hFs, __nv_bfloat16* hBs) {
    if (blockIdx.x == 0 && blockIdx.y == 0 && threadIdx.x == 0) {
        g_barc = 0;
        g_barg = 0u;
    }
    float* h = blockIdx.y ? hB : hF;
    __nv_bfloat16* hp = blockIdx.y ? hBs : hFs;
    int i = blockIdx.x * blockDim.x + threadIdx.x;
    if (i >= NN * GH) return;
    h[i] = 0.f;
    hp[i] = __float2bfloat16(0.f);
    hp[NN * GH + i] = __float2bfloat16(0.f);
}

// ---------------- final reductions ----------------
__global__ void k_colmean(const float* __restrict__ hf, const float* __restrict__ hb,
                          float* __restrict__ mean) {
    int j = blockIdx.x;
    const float* base = (j < GH) ? (hf + j) : (hb + (j - GH));
    float s = 0.f;
    for (int n = threadIdx.x; n < NN; n += blockDim.x) s += base[(size_t)n * GH];
    __shared__ float sh[256];
    sh[threadIdx.x] = s;
    __syncthreads();
    for (int o = 128; o; o >>= 1) {
        if (threadIdx.x < o) sh[threadIdx.x] += sh[threadIdx.x + o];
        __syncthreads();
    }
    if (threadIdx.x == 0) mean[j] = sh[0] * (1.f / (float)NN);
}

__global__ void k_fc(const float* __restrict__ w, const float* __restrict__ b,
                     const float* __restrict__ mean, float* __restrict__ out) {
    int i = blockIdx.x;
    float s = 0.f;
    for (int j = threadIdx.x; j < 2 * GH; j += blockDim.x) s += w[i * 2 * GH + j] * mean[j];
    __shared__ float sh[128];
    sh[threadIdx.x] = s;
    __syncthreads();
    for (int o = 64; o; o >>= 1) {
        if (threadIdx.x < o) sh[threadIdx.x] += sh[threadIdx.x + o];
        __syncthreads();
    }
    if (threadIdx.x == 0) out[i] = sh[0] + b[i];
}

// ---------------- host ----------------
static const int GEMM_SMEM = 2 * 2 * 128 * 128;   // 65536 (2 stages, 2 blocks/SM)

extern "C" void kernel_launch(void* const* d_in, const int* in_sizes, int n_in,
                              void* d_out, int out_size) {
    const float* x        = (const float*)d_in[0];
    const float* edge_ea  = (const float*)d_in[1];
    const int*   edge_src = (const int*)  d_in[2];
    const int*   edge_dst = (const int*)  d_in[3];
    const float* gat1_wl  = (const float*)d_in[4];
    const float* gat1_wr  = (const float*)d_in[5];
    const float* gat1_we  = (const float*)d_in[6];
    const float* gat1_att = (const float*)d_in[7];
    const float* gat1_b   = (const float*)d_in[8];
    const float* gat2_wl  = (const float*)d_in[9];
    const float* gat2_wr  = (const float*)d_in[10];
    const float* gat2_we  = (const float*)d_in[11];
    const float* gat2_att = (const float*)d_in[12];
    const float* gat2_b   = (const float*)d_in[13];
    const float* wih_f    = (const float*)d_in[14];
    const float* whh_f    = (const float*)d_in[15];
    const float* bih_f    = (const float*)d_in[16];
    const float* bhh_f    = (const float*)d_in[17];
    const float* wih_b    = (const float*)d_in[18];
    const float* whh_b    = (const float*)d_in[19];
    const float* bih_b    = (const float*)d_in[20];
    const float* bhh_b    = (const float*)d_in[21];
    const float* fc_w     = (const float*)d_in[22];
    const float* fc_b     = (const float*)d_in[23];
    float* out = (float*)d_out;

    cudaFuncSetAttribute(tgemm, cudaFuncAttributeMaxDynamicSharedMemorySize, GEMM_SMEM);
    cudaFuncSetAttribute(tgemm_b2, cudaFuncAttributeMaxDynamicSharedMemorySize, GEMM_SMEM);
    cudaFuncSetAttribute(chain_persist, cudaFuncAttributeMaxDynamicSharedMemorySize, GEMM_SMEM);

    float *p_degf, *p_loopsum, *p_adj_ea, *p_ghF, *p_ghB, *p_hf, *p_hb, *p_mean;
    int *p_cnt, *p_rowptr, *p_fill, *p_adj_src;
    __nv_bfloat16 *p_w1s, *p_w2s, *p_hfs, *p_hbs;
    __nv_bfloat16 *p_wihs_f, *p_wihs_b, *p_whhs_f, *p_whhs_b;
    char *arA, *arB, *arC;
    cudaGetSymbolAddress((void**)&p_degf, g_degf);
    cudaGetSymbolAddress((void**)&p_loopsum, g_loopsum);
    cudaGetSymbolAddress((void**)&p_cnt, g_cnt);
    cudaGetSymbolAddress((void**)&p_rowptr, g_rowptr);
    cudaGetSymbolAddress((void**)&p_fill, g_fill);
    cudaGetSymbolAddress((void**)&p_adj_src, g_adj_src);
    cudaGetSymbolAddress((void**)&p_adj_ea, g_adj_ea);
    cudaGetSymbolAddress((void**)&p_ghF, g_ghF);
    cudaGetSymbolAddress((void**)&p_ghB, g_ghB);
    cudaGetSymbolAddress((void**)&p_hf,  g_hf);
    cudaGetSymbolAddress((void**)&p_hb,  g_hb);
    cudaGetSymbolAddress((void**)&p_mean, g_mean);
    cudaGetSymbolAddress((void**)&p_w1s, g_w1s);
    cudaGetSymbolAddress((void**)&p_w2s, g_w2s);
    cudaGetSymbolAddress((void**)&p_hfs, g_hfs);
    cudaGetSymbolAddress((void**)&p_hbs, g_hbs);
    cudaGetSymbolAddress((void**)&p_wihs_f, g_wihs_f);
    cudaGetSymbolAddress((void**)&p_wihs_b, g_wihs_b);
    cudaGetSymbolAddress((void**)&p_whhs_f, g_whhs_f);
    cudaGetSymbolAddress((void**)&p_whhs_b, g_whhs_b);
    cudaGetSymbolAddress((void**)&arA, g_arenaA);
    cudaGetSymbolAddress((void**)&arB, g_arenaB);
    cudaGetSymbolAddress((void**)&arC, g_arenaC);

    // arena-carved pointers (phase-disjoint lifetimes)
    float*         p_xlr1 = (float*)arA;
    float*         p_giF  = (float*)arA;
    __nv_bfloat16* p_h1s  = (__nv_bfloat16*)arB;
    float*         p_giB  = (float*)arB;
    __nv_bfloat16* p_xs   = (__nv_bfloat16*)arC;
    __nv_bfloat16* p_embs = (__nv_bfloat16*)arC;
    float*         p_xlr2 = (float*)(arC + 81920000);

    const int TB = 256;
    const size_t XPL   = (size_t)TT * NN * INC;
    const size_t H1PL  = (size_t)TT * NN * F1;
    const size_t EMBPL = (size_t)TT * NN * HIDC;
    const size_t W1PL  = (size_t)2 * F1 * INC;
    const size_t W2PL  = (size_t)2 * HIDC * F1;
    const size_t WIHPL = (size_t)G3 * HIDC;

    // ---- x split + GAT weight prep (no CSR dependency) ----
    {
        size_t nx = (size_t)TT * NN * INC;
        k_split<<<(int)((nx + TB - 1) / TB), TB>>>(x, p_xs, nx);
        dim3 b(32, 8);
        k_transpose_split<<<dim3(F1 / 32, INC / 32), b>>>(gat1_wl, p_w1s, INC, F1, W1PL);
        k_transpose_split<<<dim3(F1 / 32, INC / 32), b>>>(gat1_wr, p_w1s + (size_t)F1 * INC, INC, F1, W1PL);
        k_transpose_split<<<dim3(HIDC / 32, F1 / 32), b>>>(gat2_wl, p_w2s, F1, HIDC, W2PL);
        k_transpose_split<<<dim3(HIDC / 32, F1 / 32), b>>>(gat2_wr, p_w2s + (size_t)HIDC * F1, F1, HIDC, W2PL);
    }

    // ---- big GAT1 GEMM ----
    tgemm<<<dim3((2 * F1) / 128, (TT * NN + 127) / 128), 256, GEMM_SMEM>>>(
        p_xs, p_xs + XPL, p_w1s, p_w1s + W1PL, p_xlr1, TT * NN, 2 * F1, INC);

    // ---- CSR precompute ----
    k_init<<<(3 * NN + TB - 1) / TB, TB>>>(p_degf, p_loopsum, p_cnt, p_fill);
    k_count<<<(EE + TB - 1) / TB, TB>>>(edge_ea, edge_dst, p_degf, p_loopsum, p_cnt);
    k_scan<<<1, 1024>>>(p_cnt, p_rowptr);
    k_scatter_e<<<(EE + TB - 1) / TB, TB>>>(edge_ea, edge_src, edge_dst, p_rowptr,
                                            p_fill, p_adj_src, p_adj_ea);
    k_scatter_loop<<<(NN + TB - 1) / TB, TB>>>(p_degf, p_loopsum, p_rowptr,
                                               p_fill, p_adj_src, p_adj_ea);

    // ---- GAT phase remainder ----
    gat_edge1<<<dim3(NN, TT), 256>>>(p_xlr1, gat1_we, gat1_att, gat1_b,
                                     p_rowptr, p_adj_src, p_adj_ea, p_h1s);
    tgemm<<<dim3(1, (TT * NN + 127) / 128), 256, GEMM_SMEM>>>(
        p_h1s, p_h1s + H1PL, p_w2s, p_w2s + W2PL, p_xlr2, TT * NN, 2 * HIDC, F1);
    gat_edge2<<<dim3(NN / 8, TT), 256>>>(p_xlr2, gat2_we, gat2_att, gat2_b,
                                         p_rowptr, p_adj_src, p_adj_ea, p_embs);

    // ---- GRU weight splits ----
    k_split<<<(G3 * HIDC + TB - 1) / TB, TB>>>(wih_f, p_wihs_f, (size_t)G3 * HIDC);
    k_split<<<(G3 * HIDC + TB - 1) / TB, TB>>>(wih_b, p_wihs_b, (size_t)G3 * HIDC);
    k_split<<<(G3 * GH + TB - 1) / TB, TB>>>(whh_f, p_whhs_f, (size_t)G3 * GH);
    k_split<<<(G3 * GH + TB - 1) / TB, TB>>>(whh_b, p_whhs_b, (size_t)G3 * GH);

    // ---- batched gi GEMMs (both directions, all T) ----
    tgemm_b2<<<dim3(G3 / 128, (TT * NN + 127) / 128, 2), 256, GEMM_SMEM>>>(
        p_embs, p_embs + EMBPL, p_wihs_f, p_wihs_f + WIHPL, p_giF,
        p_embs, p_embs + EMBPL, p_wihs_b, p_wihs_b + WIHPL, p_giB,
        TT * NN, G3, HIDC);

    // ---- GRU chain: ONE persistent launch with software grid barrier -------
    k_zero_h2<<<dim3((NN * GH + TB - 1) / TB, 2), TB>>>(p_hf, p_hb, p_hfs, p_hbs);
    chain_persist<<<NPERS, 256, GEMM_SMEM>>>(
        p_hfs, p_hbs, p_whhs_f, p_whhs_b, p_ghF, p_ghB,
        p_giF, p_giB, bih_f, bhh_f, bih_b, bhh_b, p_hf, p_hb);

    // ---- mean + FC ----
    k_colmean<<<2 * GH, 256>>>(p_hf, p_hb, p_mean);
    k_fc<<<33, 128>>>(fc_w, fc_b, p_mean, out);
}

// round 17
// speedup vs baseline: 1.0838x; 1.0838x over previous
#include <cuda_runtime.h>
#include <cuda_bf16.h>
#include <cstdint>

#define NN     10000
#define EE     160000
#define ENTOT  (EE + NN)
#define TT     32
#define INC    128
#define HIDC   64
#define NHEADS 8
#define F1     512        // NHEADS * HID
#define GH     256
#define G3     768        // 3 * GH

// -------- phase-overlapped arenas (disjoint lifetimes; <2GB each) -----------
#define ARENA_A_BYTES ((size_t)TT * NN * 2 * F1 * 4)            // 1,310,720,000
#define ARENA_B_BYTES ((size_t)TT * NN * G3 * 4)                //   983,040,000
#define ARENA_C_REAL  ((size_t)245760000)
__device__ __align__(256) char g_arenaA[ARENA_A_BYTES];
__device__ __align__(256) char g_arenaB[ARENA_B_BYTES];
__device__ __align__(256) char g_arenaC[ARENA_C_REAL];

// ---------------- small persistent scratch ----------------
__device__ float g_degf[NN];
__device__ float g_loopsum[NN * 3];
__device__ int   g_cnt[NN];
__device__ int   g_rowptr[NN + 1];
__device__ int   g_fill[NN];
__device__ int   g_adj_src[ENTOT];
__device__ float g_adj_ea[ENTOT * 3];
__device__ float g_ghF[NN * G3];
__device__ float g_ghB[NN * G3];
__device__ float g_mean[2 * GH];
__device__ __nv_bfloat16 g_w1s [2 * 2 * F1 * INC];
__device__ __nv_bfloat16 g_w2s [2 * 2 * HIDC * F1];
__device__ __nv_bfloat16 g_hfs [2 * NN * GH];
__device__ __nv_bfloat16 g_hbs [2 * NN * GH];
__device__ __nv_bfloat16 g_wihs_f[2 * G3 * HIDC];
__device__ __nv_bfloat16 g_wihs_b[2 * G3 * HIDC];
__device__ __nv_bfloat16 g_whhs_f[2 * G3 * GH];
__device__ __nv_bfloat16 g_whhs_b[2 * G3 * GH];

// ---------------- helpers ----------------
#define SWZ(off) ((off) ^ (((off) >> 3) & 0x70))

__device__ __forceinline__ uint32_t smem_u32(const void* p) {
    uint32_t a;
    asm("{ .reg .u64 t; cvta.to.shared.u64 t, %1; cvt.u32.u64 %0, t; }" : "=r"(a) : "l"(p));
    return a;
}
__device__ __forceinline__ void cp_async16(uint32_t dst, const void* src, int sz) {
    asm volatile("cp.async.ca.shared.global [%0], [%1], 16, %2;"
                 :: "r"(dst), "l"(src), "r"(sz) : "memory");
}
__device__ __forceinline__ void cp_commit() {
    asm volatile("cp.async.commit_group;" ::: "memory");
}
__device__ __forceinline__ void cp_wait1() {
    asm volatile("cp.async.wait_group 1;" ::: "memory");
}
__device__ __forceinline__ void cp_wait0() {
    asm volatile("cp.async.wait_group 0;" ::: "memory");
}
__device__ __forceinline__ void ldsm_x4(uint32_t* r, uint32_t addr) {
    asm volatile("ldmatrix.sync.aligned.m8n8.x4.shared.b16 {%0,%1,%2,%3}, [%4];"
                 : "=r"(r[0]), "=r"(r[1]), "=r"(r[2]), "=r"(r[3]) : "r"(addr));
}
__device__ __forceinline__ void mma_bf16(float* c, const uint32_t* a, uint32_t b0, uint32_t b1) {
    asm volatile("mma.sync.aligned.m16n8k16.row.col.f32.bf16.bf16.f32 "
                 "{%0,%1,%2,%3}, {%4,%5,%6,%7}, {%8,%9}, {%0,%1,%2,%3};"
                 : "+f"(c[0]), "+f"(c[1]), "+f"(c[2]), "+f"(c[3])
                 : "r"(a[0]), "r"(a[1]), "r"(a[2]), "r"(a[3]), "r"(b0), "r"(b1));
}
__device__ __forceinline__ void split_bf16(float v, __nv_bfloat16& hi, __nv_bfloat16& lo) {
    hi = __float2bfloat16_rn(v);
    lo = __float2bfloat16_rn(v - __bfloat162float(hi));
}

// ---- bf16x3 emulated-fp32 GEMM body: C[M,N] = A[M,K] @ BT[N,K]^T ------------
// 2-stage cp.async pipeline, 64KB smem, 2 blocks/SM co-residency.
__device__ __forceinline__ void gemm_body(
    const __nv_bfloat16* __restrict__ Ahi, const __nv_bfloat16* __restrict__ Alo,
    const __nv_bfloat16* __restrict__ Bhi, const __nv_bfloat16* __restrict__ Blo,
    float* __restrict__ C, int M, int N, int K, char* smem, int bm, int bn)
{
    constexpr int TSZ   = 128 * 128;
    constexpr int STAGE = 2 * TSZ;
    const uint32_t sbase = smem_u32(smem);
    const int t = threadIdx.x;
    const int warp = t >> 5, lane = t & 31;
    const int tI = lane >> 3, lr = lane & 7;
    const int wm0 = (warp & 1) * 64;
    const int wn0 = (warp >> 1) * 32;
    const size_t Kb = (size_t)K * 2;

    float acc[4][4][4];
    #pragma unroll
    for (int i = 0; i < 4; i++)
        #pragma unroll
        for (int j = 0; j < 4; j++)
            #pragma unroll
            for (int k = 0; k < 4; k++) acc[i][j][k] = 0.f;

    const int NC = K >> 5;

    auto load_stage = [&](int s, int c) {
        uint32_t sa = sbase + s * STAGE;
        uint32_t sb = sa + TSZ;
        int k0b = c << 6;
        #pragma unroll
        for (int i = 0; i < 4; i++) {
            int idx = t + i * 256;
            int row = idx >> 3, c8 = idx & 7;
            const char* base = (const char*)((c8 & 4) ? Alo : Ahi);
            const char* src = base + (size_t)(bm + row) * Kb + k0b + (c8 & 3) * 16;
            int sz = (bm + row < M) ? 16 : 0;
            cp_async16(sa + SWZ((row << 7) | (c8 << 4)), src, sz);
        }
        #pragma unroll
        for (int i = 0; i < 4; i++) {
            int idx = t + i * 256;
            int row = idx >> 3, c8 = idx & 7;
            const char* base = (const char*)((c8 & 4) ? Blo : Bhi);
            const char* src = base + (size_t)(bn + row) * Kb + k0b + (c8 & 3) * 16;
            cp_async16(sb + SWZ((row << 7) | (c8 << 4)), src, 16);
        }
        cp_commit();
    };

    load_stage(0, 0);

    for (int c = 0; c < NC; c++) {
        if (c + 1 < NC) { load_stage((c + 1) & 1, c + 1); cp_wait1(); }
        else            { cp_wait0(); }
        __syncthreads();

        uint32_t sa = sbase + (c & 1) * STAGE;
        uint32_t sb = sa + TSZ;
        #pragma unroll
        for (int ks = 0; ks < 2; ks++) {
            uint32_t Ah[4][4], Al[4][4], Bh[2][4], Bl[2][4];
            #pragma unroll
            for (int ma = 0; ma < 4; ma++) {
                int row = wm0 + ma * 16 + ((tI & 1) << 3) + lr;
                int kb = (ks << 5) | ((tI >> 1) << 4);
                ldsm_x4(Ah[ma], sa + SWZ((row << 7) | kb));
                ldsm_x4(Al[ma], sa + SWZ((row << 7) | (64 + kb)));
            }
            #pragma unroll
            for (int nb = 0; nb < 2; nb++) {
                int row = wn0 + nb * 16 + ((tI >> 1) << 3) + lr;
                int kb = (ks << 5) | ((tI & 1) << 4);
                ldsm_x4(Bh[nb], sb + SWZ((row << 7) | kb));
                ldsm_x4(Bl[nb], sb + SWZ((row << 7) | (64 + kb)));
            }
            #pragma unroll
            for (int ma = 0; ma < 4; ma++)
                #pragma unroll
                for (int na = 0; na < 4; na++) {
                    int nb = na >> 1, off = (na & 1) * 2;
                    mma_bf16(acc[ma][na], Ah[ma], Bl[nb][off], Bl[nb][off + 1]);
                    mma_bf16(acc[ma][na], Al[ma], Bh[nb][off], Bh[nb][off + 1]);
                    mma_bf16(acc[ma][na], Ah[ma], Bh[nb][off], Bh[nb][off + 1]);
                }
        }
        __syncthreads();
    }

    #pragma unroll
    for (int ma = 0; ma < 4; ma++) {
        int row = bm + wm0 + ma * 16 + (lane >> 2);
        #pragma unroll
        for (int na = 0; na < 4; na++) {
            int col = bn + wn0 + na * 8 + 2 * (lane & 3);
            if (row < M)
                *reinterpret_cast<float2*>(&C[(size_t)row * N + col]) =
                    make_float2(acc[ma][na][0], acc[ma][na][1]);
            if (row + 8 < M)
                *reinterpret_cast<float2*>(&C[(size_t)(row + 8) * N + col]) =
                    make_float2(acc[ma][na][2], acc[ma][na][3]);
        }
    }
}

// ---- single-direction GRU gate body: h lives ONLY in bf16 hi/lo planes -----
__device__ __forceinline__ void gate_body(
    const float* __restrict__ gi, const float* __restrict__ gh,
    const float* __restrict__ bih, const float* __restrict__ bhh,
    __nv_bfloat16* __restrict__ hp, int gid)
{
    int q = gid * 256 + threadIdx.x;
    if (q >= NN * GH / 4) return;
    int n = q / (GH / 4), j = (q % (GH / 4)) * 4;
    const float* gin = gi + (size_t)n * G3;
    const float* ghn = gh + (size_t)n * G3;
    float4 gr = *(const float4*)(gin + j);
    float4 gz = *(const float4*)(gin + GH + j);
    float4 gn = *(const float4*)(gin + 2 * GH + j);
    float4 hr = *(const float4*)(ghn + j);
    float4 hz = *(const float4*)(ghn + GH + j);
    float4 hn4 = *(const float4*)(ghn + 2 * GH + j);
    float4 br = *(const float4*)(bih + j);
    float4 bz = *(const float4*)(bih + GH + j);
    float4 bn = *(const float4*)(bih + 2 * GH + j);
    float4 cr = *(const float4*)(bhh + j);
    float4 cz = *(const float4*)(bhh + GH + j);
    float4 cn = *(const float4*)(bhh + 2 * GH + j);
    size_t hidx = (size_t)n * GH + j;
    // reconstruct h from hi/lo planes (exact to ~2^-17 relative)
    __nv_bfloat162 h0 = *(const __nv_bfloat162*)(hp + hidx);
    __nv_bfloat162 h1 = *(const __nv_bfloat162*)(hp + hidx + 2);
    __nv_bfloat162 l0 = *(const __nv_bfloat162*)(hp + NN * GH + hidx);
    __nv_bfloat162 l1 = *(const __nv_bfloat162*)(hp + NN * GH + hidx + 2);
    float4 hv;
    hv.x = __bfloat162float(h0.x) + __bfloat162float(l0.x);
    hv.y = __bfloat162float(h0.y) + __bfloat162float(l0.y);
    hv.z = __bfloat162float(h1.x) + __bfloat162float(l1.x);
    hv.w = __bfloat162float(h1.y) + __bfloat162float(l1.y);
    float4 ho;
    #pragma unroll
    for (int k = 0; k < 4; k++) {
        float grk = (&gr.x)[k] + (&br.x)[k], hrk = (&hr.x)[k] + (&cr.x)[k];
        float gzk = (&gz.x)[k] + (&bz.x)[k], hzk = (&hz.x)[k] + (&cz.x)[k];
        float gnk = (&gn.x)[k] + (&bn.x)[k], hnk = (&hn4.x)[k] + (&cn.x)[k];
        float r = 1.f / (1.f + __expf(-(grk + hrk)));
        float z = 1.f / (1.f + __expf(-(gzk + hzk)));
        float nv = tanhf(gnk + r * hnk);
        (&ho.x)[k] = (1.f - z) * nv + z * (&hv.x)[k];
    }
    #pragma unroll
    for (int k = 0; k < 4; k++) {
        __nv_bfloat16 hi, lo;
        split_bf16((&ho.x)[k], hi, lo);
        hp[hidx + k] = hi;
        hp[NN * GH + hidx + k] = lo;
    }
}

__global__ void __launch_bounds__(256, 2) tgemm(
    const __nv_bfloat16* __restrict__ Ahi, const __nv_bfloat16* __restrict__ Alo,
    const __nv_bfloat16* __restrict__ Bhi, const __nv_bfloat16* __restrict__ Blo,
    float* __restrict__ C, int M, int N, int K)
{
    extern __shared__ char smem[];
    gemm_body(Ahi, Alo, Bhi, Blo, C, M, N, K, smem, blockIdx.y * 128, blockIdx.x * 128);
}

__global__ void __launch_bounds__(256, 2) tgemm_b2(
    const __nv_bfloat16* Ahi0, const __nv_bfloat16* Alo0,
    const __nv_bfloat16* Bhi0, const __nv_bfloat16* Blo0, float* C0,
    const __nv_bfloat16* Ahi1, const __nv_bfloat16* Alo1,
    const __nv_bfloat16* Bhi1, const __nv_bfloat16* Blo1, float* C1,
    int M, int N, int K)
{
    extern __shared__ char smem[];
    if (blockIdx.z == 0) gemm_body(Ahi0, Alo0, Bhi0, Blo0, C0, M, N, K, smem,
                                   blockIdx.y * 128, blockIdx.x * 128);
    else                 gemm_body(Ahi1, Alo1, Bhi1, Blo1, C1, M, N, K, smem,
                                   blockIdx.y * 128, blockIdx.x * 128);
}

// ---- chain step: GEMM (one direction) + gate (other direction) in ONE launch
#define NBGEMM (6 * 79)        // (G3/128) * ceil(NN/128) = 474
#define NBGATE 2500            // NN*GH/4 / 256
__global__ void __launch_bounds__(256, 2) chain_step(
    const __nv_bfloat16* Ahi, const __nv_bfloat16* Alo,
    const __nv_bfloat16* Bhi, const __nv_bfloat16* Blo, float* Cgh,
    const float* gi, const float* gh, const float* bih, const float* bhh,
    __nv_bfloat16* hp, int do_gate)
{
    extern __shared__ char smem[];
    if (blockIdx.x < NBGEMM) {
        int bx = blockIdx.x % (G3 / 128);
        int by = blockIdx.x / (G3 / 128);
        gemm_body(Ahi, Alo, Bhi, Blo, Cgh, NN, G3, GH, smem, by * 128, bx * 128);
    } else if (do_gate) {
        gate_body(gi, gh, bih, bhh, hp, blockIdx.x - NBGEMM);
    }
}

// final gate-only launch (one direction)
__global__ void gate_one(const float* gi, const float* gh,
                         const float* bih, const float* bhh,
                         __nv_bfloat16* hp)
{
    gate_body(gi, gh, bih, bhh, hp, blockIdx.x);
}

// ------------- transpose + split ---------------------------------------------
__global__ void k_transpose_split(const float* __restrict__ in, __nv_bfloat16* __restrict__ out,
                                  int R, int Ccols, size_t plane) {
    __shared__ float tile[32][33];
    int c0 = blockIdx.x * 32, r0 = blockIdx.y * 32;
    int x = threadIdx.x, y = threadIdx.y;
    for (int j = 0; j < 32; j += 8) {
        int r = r0 + y + j, c = c0 + x;
        if (r < R && c < Ccols) tile[y + j][x] = in[(size_t)r * Ccols + c];
    }
    __syncthreads();
    for (int j = 0; j < 32; j += 8) {
        int c = c0 + y + j, r = r0 + x;
        if (c < Ccols && r < R) {
            __nv_bfloat16 hi, lo;
            split_bf16(tile[x][y + j], hi, lo);
            out[(size_t)c * R + r] = hi;
            out[plane + (size_t)c * R + r] = lo;
        }
    }
}

__global__ void k_split(const float* __restrict__ in, __nv_bfloat16* __restrict__ out, size_t n) {
    size_t i = (size_t)blockIdx.x * blockDim.x + threadIdx.x;
    if (i >= n) return;
    __nv_bfloat16 hi, lo;
    split_bf16(in[i], hi, lo);
    out[i] = hi;
    out[n + i] = lo;
}

// ---------------- init (fused zeros) ----------------
__global__ void k_init(float* degf, float* loopsum, int* cnt, int* fill) {
    int i = blockIdx.x * blockDim.x + threadIdx.x;
    if (i < NN) { degf[i] = 0.f; cnt[i] = 0; fill[i] = 0; }
    if (i < 3 * NN) loopsum[i] = 0.f;
}

// ---------------- CSR precompute ----------------
__global__ void k_count(const float* __restrict__ ea, const int* __restrict__ dst,
                        float* degf, float* loopsum, int* cnt) {
    int e = blockIdx.x * blockDim.x + threadIdx.x;
    if (e >= EE) return;
    int d = dst[e];
    atomicAdd(&degf[d], 1.f);
    atomicAdd(&cnt[d], 1);
    atomicAdd(&loopsum[d * 3 + 0], ea[e * 3 + 0]);
    atomicAdd(&loopsum[d * 3 + 1], ea[e * 3 + 1]);
    atomicAdd(&loopsum[d * 3 + 2], ea[e * 3 + 2]);
}

__global__ void k_scan(const int* __restrict__ cnt, int* __restrict__ rowptr) {
    __shared__ int tmp[1024];
    __shared__ int carry_s;
    int tid = threadIdx.x;
    if (tid == 0) { carry_s = 0; rowptr[0] = 0; }
    __syncthreads();
    for (int base = 0; base < NN; base += 1024) {
        int i = base + tid;
        int v = (i < NN) ? (cnt[i] + 1) : 0;
        tmp[tid] = v;
        __syncthreads();
        #pragma unroll
        for (int off = 1; off < 1024; off <<= 1) {
            int tv = (tid >= off) ? tmp[tid - off] : 0;
            __syncthreads();
            tmp[tid] += tv;
            __syncthreads();
        }
        if (i < NN) rowptr[i + 1] = carry_s + tmp[tid];
        __syncthreads();
        if (tid == 0) carry_s += tmp[1023];
        __syncthreads();
    }
}

__global__ void k_scatter_e(const float* __restrict__ ea, const int* __restrict__ src,
                            const int* __restrict__ dst, const int* __restrict__ rowptr,
                            int* fill, int* adj_src, float* adj_ea) {
    int e = blockIdx.x * blockDim.x + threadIdx.x;
    if (e >= EE) return;
    int d = dst[e];
    int pos = rowptr[d] + atomicAdd(&fill[d], 1);
    adj_src[pos] = src[e];
    adj_ea[pos * 3 + 0] = ea[e * 3 + 0];
    adj_ea[pos * 3 + 1] = ea[e * 3 + 1];
    adj_ea[pos * 3 + 2] = ea[e * 3 + 2];
}

__global__ void k_scatter_loop(const float* __restrict__ degf, const float* __restrict__ loopsum,
                               const int* __restrict__ rowptr, int* fill,
                               int* adj_src, float* adj_ea) {
    int n = blockIdx.x * blockDim.x + threadIdx.x;
    if (n >= NN) return;
    int pos = rowptr[n] + atomicAdd(&fill[n], 1);
    adj_src[pos] = n;
    float dm = fmaxf(degf[n], 1.f);
    adj_ea[pos * 3 + 0] = loopsum[n * 3 + 0] / dm;
    adj_ea[pos * 3 + 1] = loopsum[n * 3 + 1] / dm;
    adj_ea[pos * 3 + 2] = loopsum[n * 3 + 2] / dm;
}

// ---- GAT1 edge kernel: 2-edge-unrolled online softmax, warp == head --------
__global__ void __launch_bounds__(256) gat_edge1(
    const float* __restrict__ xlr,
    const float* __restrict__ we, const float* __restrict__ att,
    const float* __restrict__ bias,
    const int* __restrict__ rowptr, const int* __restrict__ adj_src,
    const float* __restrict__ adj_ea,
    __nv_bfloat16* __restrict__ outp)
{
    constexpr size_t H1PL = (size_t)TT * NN * F1;
    int n = blockIdx.x, tc = blockIdx.y;
    int warp = threadIdx.x >> 5, lane = threadIdx.x & 31;
    int c0 = warp * 64 + lane, c1 = c0 + 32;
    const float* base = xlr + (size_t)tc * NN * (2 * F1);
    const float* xrrow = base + (size_t)n * (2 * F1) + F1;
    float xr0 = xrrow[c0], xr1 = xrrow[c1];
    float a0 = att[c0], a1 = att[c1];
    float w00 = we[c0], w01 = we[F1 + c0], w02 = we[2 * F1 + c0];
    float w10 = we[c1], w11 = we[F1 + c1], w12 = we[2 * F1 + c1];
    int beg = rowptr[n], end = rowptr[n + 1];
    float m_run = -1e30f, s_run = 0.f, acc0 = 0.f, acc1 = 0.f;

    for (int p = beg; p < end; p += 2) {
        bool has2 = (p + 1 < end);
        int sa = adj_src[p];
        int sb = has2 ? adj_src[p + 1] : sa;
        float ea0 = adj_ea[3 * p + 0], ea1 = adj_ea[3 * p + 1], ea2 = adj_ea[3 * p + 2];
        float eb0 = 0.f, eb1 = 0.f, eb2 = 0.f;
        if (has2) { eb0 = adj_ea[3 * p + 3]; eb1 = adj_ea[3 * p + 4]; eb2 = adj_ea[3 * p + 5]; }
        const float* ra = base + (size_t)sa * (2 * F1);
        const float* rb = base + (size_t)sb * (2 * F1);
        float xa0 = __ldg(&ra[c0]), xa1 = __ldg(&ra[c1]);
        float xb0 = __ldg(&rb[c0]), xb1 = __ldg(&rb[c1]);
        float ma0 = xa0 + xr0 + ea0 * w00 + ea1 * w01 + ea2 * w02;
        float ma1 = xa1 + xr1 + ea0 * w10 + ea1 * w11 + ea2 * w12;
        float mb0 = xb0 + xr0 + eb0 * w00 + eb1 * w01 + eb2 * w02;
        float mb1 = xb1 + xr1 + eb0 * w10 + eb1 * w11 + eb2 * w12;
        ma0 = (ma0 > 0.f) ? ma0 : 0.2f * ma0;
        ma1 = (ma1 > 0.f) ? ma1 : 0.2f * ma1;
        mb0 = (mb0 > 0.f) ? mb0 : 0.2f * mb0;
        mb1 = (mb1 > 0.f) ? mb1 : 0.2f * mb1;
        float pa = ma0 * a0 + ma1 * a1;
        float pb = mb0 * a0 + mb1 * a1;
        #pragma unroll
        for (int o = 16; o; o >>= 1) {
            pa += __shfl_xor_sync(0xffffffffu, pa, o);
            pb += __shfl_xor_sync(0xffffffffu, pb, o);
        }
        float pm = has2 ? fmaxf(pa, pb) : pa;
        float newm = fmaxf(m_run, pm);
        float sc = __expf(m_run - newm);
        float wa = __expf(pa - newm);
        float wb = has2 ? __expf(pb - newm) : 0.f;
        s_run = s_run * sc + wa + wb;
        acc0 = acc0 * sc + wa * xa0 + wb * xb0;
        acc1 = acc1 * sc + wa * xa1 + wb * xb1;
        m_run = newm;
    }
    float inv = 1.f / s_run;
    float o0 = acc0 * inv + bias[c0];
    float o1 = acc1 * inv + bias[c1];
    o0 = (o0 > 0.f) ? o0 : (__expf(o0) - 1.f);
    o1 = (o1 > 0.f) ? o1 : (__expf(o1) - 1.f);
    size_t orow = ((size_t)tc * NN + n) * F1;
    __nv_bfloat16 hi, lo;
    split_bf16(o0, hi, lo); outp[orow + c0] = hi; outp[H1PL + orow + c0] = lo;
    split_bf16(o1, hi, lo); outp[orow + c1] = hi; outp[H1PL + orow + c1] = lo;
}

// ---- GAT2 edge kernel: 2-edge-unrolled, warp == node (1 head) --------------
__global__ void __launch_bounds__(256) gat_edge2(
    const float* __restrict__ xlr,
    const float* __restrict__ we, const float* __restrict__ att,
    const float* __restrict__ bias,
    const int* __restrict__ rowptr, const int* __restrict__ adj_src,
    const float* __restrict__ adj_ea,
    __nv_bfloat16* __restrict__ outp)
{
    constexpr size_t EMBPL = (size_t)TT * NN * HIDC;
    int warp = threadIdx.x >> 5, lane = threadIdx.x & 31;
    int n = blockIdx.x * 8 + warp, tc = blockIdx.y;
    int c0 = lane, c1 = lane + 32;
    const float* base = xlr + (size_t)tc * NN * (2 * HIDC);
    const float* xrrow = base + (size_t)n * (2 * HIDC) + HIDC;
    float xr0 = xrrow[c0], xr1 = xrrow[c1];
    float a0 = att[c0], a1 = att[c1];
    float w00 = we[c0], w01 = we[HIDC + c0], w02 = we[2 * HIDC + c0];
    float w10 = we[c1], w11 = we[HIDC + c1], w12 = we[2 * HIDC + c1];
    int beg = rowptr[n], end = rowptr[n + 1];
    float m_run = -1e30f, s_run = 0.f, acc0 = 0.f, acc1 = 0.f;

    for (int p = beg; p < end; p += 2) {
        bool has2 = (p + 1 < end);
        int sa = adj_src[p];
        int sb = has2 ? adj_src[p + 1] : sa;
        float ea0 = adj_ea[3 * p + 0], ea1 = adj_ea[3 * p + 1], ea2 = adj_ea[3 * p + 2];
        float eb0 = 0.f, eb1 = 0.f, eb2 = 0.f;
        if (has2) { eb0 = adj_ea[3 * p + 3]; eb1 = adj_ea[3 * p + 4]; eb2 = adj_ea[3 * p + 5]; }
        const float* ra = base + (size_t)sa * (2 * HIDC);
        const float* rb = base + (size_t)sb * (2 * HIDC);
        float xa0 = __ldg(&ra[c0]), xa1 = __ldg(&ra[c1]);
        float xb0 = __ldg(&rb[c0]), xb1 = __ldg(&rb[c1]);
        float ma0 = xa0 + xr0 + ea0 * w00 + ea1 * w01 + ea2 * w02;
        float ma1 = xa1 + xr1 + ea0 * w10 + ea1 * w11 + ea2 * w12;
        float mb0 = xb0 + xr0 + eb0 * w00 + eb1 * w01 + eb2 * w02;
        float mb1 = xb1 + xr1 + eb0 * w10 + eb1 * w11 + eb2 * w12;
        ma0 = (ma0 > 0.f) ? ma0 : 0.2f * ma0;
        ma1 = (ma1 > 0.f) ? ma1 : 0.2f * ma1;
        mb0 = (mb0 > 0.f) ? mb0 : 0.2f * mb0;
        mb1 = (mb1 > 0.f) ? mb1 : 0.2f * mb1;
        float pa = ma0 * a0 + ma1 * a1;
        float pb = mb0 * a0 + mb1 * a1;
        #pragma unroll
        for (int o = 16; o; o >>= 1) {
            pa += __shfl_xor_sync(0xffffffffu, pa, o);
            pb += __shfl_xor_sync(0xffffffffu, pb, o);
        }
        float pm = has2 ? fmaxf(pa, pb) : pa;
        float newm = fmaxf(m_run, pm);
        float sc = __expf(m_run - newm);
        float wa = __expf(pa - newm);
        float wb = has2 ? __expf(pb - newm) : 0.f;
        s_run = s_run * sc + wa + wb;
        acc0 = acc0 * sc + wa * xa0 + wb * xb0;
        acc1 = acc1 * sc + wa * xa1 + wb * xb1;
        m_run = newm;
    }
    float inv = 1.f / s_run;
    float o0 = acc0 * inv + bias[c0];
    float o1 = acc1 * inv + bias[c1];
    o0 = (o0 > 0.f) ? o0 : (__expf(o0) - 1.f);
    o1 = (o1 > 0.f) ? o1 : (__expf(o1) - 1.f);
    size_t orow = ((size_t)tc * NN + n) * HIDC;
    __nv_bfloat16 hi, lo;
    split_bf16(o0, hi, lo); outp[orow + c0] = hi; outp[EMBPL + orow + c0] = lo;
    split_bf16(o1, hi, lo); outp[orow + c1] = hi; outp[EMBPL + orow + c1] = lo;
}

__global__ void k_zero_h2(__nv_bfloat16* hFs, __nv_bfloat16* hBs) {
    __nv_bfloat16* hp = blockIdx.y ? hBs : hFs;
    int i = blockIdx.x * blockDim.x + threadIdx.x;
    if (i >= NN * GH) return;
    hp[i] = __float2bfloat16(0.f);
    hp[NN * GH + i] = __float2bfloat16(0.f);
}

// ---------------- final reductions (reconstruct h from planes) --------------
__global__ void k_colmean(const __nv_bfloat16* __restrict__ hfs,
                          const __nv_bfloat16* __restrict__ hbs,
                          float* __restrict__ mean) {
    int j = blockIdx.x;
    const __nv_bfloat16* hp = (j < GH) ? hfs : hbs;
    int col = (j < GH) ? j : (j - GH);
    float s = 0.f;
    for (int n = threadIdx.x; n < NN; n += blockDim.x) {
        size_t idx = (size_t)n * GH + col;
        s += __bfloat162float(hp[idx]) + __bfloat162float(hp[NN * GH + idx]);
    }
    __shared__ float sh[256];
    sh[threadIdx.x] = s;
    __syncthreads();
    for (int o = 128; o; o >>= 1) {
        if (threadIdx.x < o) sh[threadIdx.x] += sh[threadIdx.x + o];
        __syncthreads();
    }
    if (threadIdx.x == 0) mean[j] = sh[0] * (1.f / (float)NN);
}

__global__ void k_fc(const float* __restrict__ w, const float* __restrict__ b,
                     const float* __restrict__ mean, float* __restrict__ out) {
    int i = blockIdx.x;
    float s = 0.f;
    for (int j = threadIdx.x; j < 2 * GH; j += blockDim.x) s += w[i * 2 * GH + j] * mean[j];
    __shared__ float sh[128];
    sh[threadIdx.x] = s;
    __syncthreads();
    for (int o = 64; o; o >>= 1) {
        if (threadIdx.x < o) sh[threadIdx.x] += sh[threadIdx.x + o];
        __syncthreads();
    }
    if (threadIdx.x == 0) out[i] = sh[0] + b[i];
}

// ---------------- host ----------------
static const int GEMM_SMEM = 2 * 2 * 128 * 128;   // 65536 (2 stages, 2 blocks/SM)

extern "C" void kernel_launch(void* const* d_in, const int* in_sizes, int n_in,
                              void* d_out, int out_size) {
    const float* x        = (const float*)d_in[0];
    const float* edge_ea  = (const float*)d_in[1];
    const int*   edge_src = (const int*)  d_in[2];
    const int*   edge_dst = (const int*)  d_in[3];
    const float* gat1_wl  = (const float*)d_in[4];
    const float* gat1_wr  = (const float*)d_in[5];
    const float* gat1_we  = (const float*)d_in[6];
    const float* gat1_att = (const float*)d_in[7];
    const float* gat1_b   = (const float*)d_in[8];
    const float* gat2_wl  = (const float*)d_in[9];
    const float* gat2_wr  = (const float*)d_in[10];
    const float* gat2_we  = (const float*)d_in[11];
    const float* gat2_att = (const float*)d_in[12];
    const float* gat2_b   = (const float*)d_in[13];
    const float* wih_f    = (const float*)d_in[14];
    const float* whh_f    = (const float*)d_in[15];
    const float* bih_f    = (const float*)d_in[16];
    const float* bhh_f    = (const float*)d_in[17];
    const float* wih_b    = (const float*)d_in[18];
    const float* whh_b    = (const float*)d_in[19];
    const float* bih_b    = (const float*)d_in[20];
    const float* bhh_b    = (const float*)d_in[21];
    const float* fc_w     = (const float*)d_in[22];
    const float* fc_b     = (const float*)d_in[23];
    float* out = (float*)d_out;

    cudaFuncSetAttribute(tgemm, cudaFuncAttributeMaxDynamicSharedMemorySize, GEMM_SMEM);
    cudaFuncSetAttribute(tgemm_b2, cudaFuncAttributeMaxDynamicSharedMemorySize, GEMM_SMEM);
    cudaFuncSetAttribute(chain_step, cudaFuncAttributeMaxDynamicSharedMemorySize, GEMM_SMEM);

    float *p_degf, *p_loopsum, *p_adj_ea, *p_ghF, *p_ghB, *p_mean;
    int *p_cnt, *p_rowptr, *p_fill, *p_adj_src;
    __nv_bfloat16 *p_w1s, *p_w2s, *p_hfs, *p_hbs;
    __nv_bfloat16 *p_wihs_f, *p_wihs_b, *p_whhs_f, *p_whhs_b;
    char *arA, *arB, *arC;
    cudaGetSymbolAddress((void**)&p_degf, g_degf);
    cudaGetSymbolAddress((void**)&p_loopsum, g_loopsum);
    cudaGetSymbolAddress((void**)&p_cnt, g_cnt);
    cudaGetSymbolAddress((void**)&p_rowptr, g_rowptr);
    cudaGetSymbolAddress((void**)&p_fill, g_fill);
    cudaGetSymbolAddress((void**)&p_adj_src, g_adj_src);
    cudaGetSymbolAddress((void**)&p_adj_ea, g_adj_ea);
    cudaGetSymbolAddress((void**)&p_ghF, g_ghF);
    cudaGetSymbolAddress((void**)&p_ghB, g_ghB);
    cudaGetSymbolAddress((void**)&p_mean, g_mean);
    cudaGetSymbolAddress((void**)&p_w1s, g_w1s);
    cudaGetSymbolAddress((void**)&p_w2s, g_w2s);
    cudaGetSymbolAddress((void**)&p_hfs, g_hfs);
    cudaGetSymbolAddress((void**)&p_hbs, g_hbs);
    cudaGetSymbolAddress((void**)&p_wihs_f, g_wihs_f);
    cudaGetSymbolAddress((void**)&p_wihs_b, g_wihs_b);
    cudaGetSymbolAddress((void**)&p_whhs_f, g_whhs_f);
    cudaGetSymbolAddress((void**)&p_whhs_b, g_whhs_b);
    cudaGetSymbolAddress((void**)&arA, g_arenaA);
    cudaGetSymbolAddress((void**)&arB, g_arenaB);
    cudaGetSymbolAddress((void**)&arC, g_arenaC);

    // arena-carved pointers (phase-disjoint lifetimes)
    float*         p_xlr1 = (float*)arA;
    float*         p_giF  = (float*)arA;
    __nv_bfloat16* p_h1s  = (__nv_bfloat16*)arB;
    float*         p_giB  = (float*)arB;
    __nv_bfloat16* p_xs   = (__nv_bfloat16*)arC;
    __nv_bfloat16* p_embs = (__nv_bfloat16*)arC;
    float*         p_xlr2 = (float*)(arC + 81920000);

    const int TB = 256;
    const size_t XPL   = (size_t)TT * NN * INC;
    const size_t H1PL  = (size_t)TT * NN * F1;
    const size_t EMBPL = (size_t)TT * NN * HIDC;
    const size_t W1PL  = (size_t)2 * F1 * INC;
    const size_t W2PL  = (size_t)2 * HIDC * F1;
    const size_t WIHPL = (size_t)G3 * HIDC;
    const size_t WHHPL = (size_t)G3 * GH;

    // ---- x split + GAT weight prep (no CSR dependency) ----
    {
        size_t nx = (size_t)TT * NN * INC;
        k_split<<<(int)((nx + TB - 1) / TB), TB>>>(x, p_xs, nx);
        dim3 b(32, 8);
        k_transpose_split<<<dim3(F1 / 32, INC / 32), b>>>(gat1_wl, p_w1s, INC, F1, W1PL);
        k_transpose_split<<<dim3(F1 / 32, INC / 32), b>>>(gat1_wr, p_w1s + (size_t)F1 * INC, INC, F1, W1PL);
        k_transpose_split<<<dim3(HIDC / 32, F1 / 32), b>>>(gat2_wl, p_w2s, F1, HIDC, W2PL);
        k_transpose_split<<<dim3(HIDC / 32, F1 / 32), b>>>(gat2_wr, p_w2s + (size_t)HIDC * F1, F1, HIDC, W2PL);
    }

    // ---- big GAT1 GEMM ----
    tgemm<<<dim3((2 * F1) / 128, (TT * NN + 127) / 128), 256, GEMM_SMEM>>>(
        p_xs, p_xs + XPL, p_w1s, p_w1s + W1PL, p_xlr1, TT * NN, 2 * F1, INC);

    // ---- CSR precompute ----
    k_init<<<(3 * NN + TB - 1) / TB, TB>>>(p_degf, p_loopsum, p_cnt, p_fill);
    k_count<<<(EE + TB - 1) / TB, TB>>>(edge_ea, edge_dst, p_degf, p_loopsum, p_cnt);
    k_scan<<<1, 1024>>>(p_cnt, p_rowptr);
    k_scatter_e<<<(EE + TB - 1) / TB, TB>>>(edge_ea, edge_src, edge_dst, p_rowptr,
                                            p_fill, p_adj_src, p_adj_ea);
    k_scatter_loop<<<(NN + TB - 1) / TB, TB>>>(p_degf, p_loopsum, p_rowptr,
                                               p_fill, p_adj_src, p_adj_ea);

    // ---- GAT phase remainder ----
    gat_edge1<<<dim3(NN, TT), 256>>>(p_xlr1, gat1_we, gat1_att, gat1_b,
                                     p_rowptr, p_adj_src, p_adj_ea, p_h1s);
    tgemm<<<dim3(1, (TT * NN + 127) / 128), 256, GEMM_SMEM>>>(
        p_h1s, p_h1s + H1PL, p_w2s, p_w2s + W2PL, p_xlr2, TT * NN, 2 * HIDC, F1);
    gat_edge2<<<dim3(NN / 8, TT), 256>>>(p_xlr2, gat2_we, gat2_att, gat2_b,
                                         p_rowptr, p_adj_src, p_adj_ea, p_embs);

    // ---- GRU weight splits ----
    k_split<<<(G3 * HIDC + TB - 1) / TB, TB>>>(wih_f, p_wihs_f, (size_t)G3 * HIDC);
    k_split<<<(G3 * HIDC + TB - 1) / TB, TB>>>(wih_b, p_wihs_b, (size_t)G3 * HIDC);
    k_split<<<(G3 * GH + TB - 1) / TB, TB>>>(whh_f, p_whhs_f, (size_t)G3 * GH);
    k_split<<<(G3 * GH + TB - 1) / TB, TB>>>(whh_b, p_whhs_b, (size_t)G3 * GH);

    // ---- batched gi GEMMs (both directions, all T) ----
    tgemm_b2<<<dim3(G3 / 128, (TT * NN + 127) / 128, 2), 256, GEMM_SMEM>>>(
        p_embs, p_embs + EMBPL, p_wihs_f, p_wihs_f + WIHPL, p_giF,
        p_embs, p_embs + EMBPL, p_wihs_b, p_wihs_b + WIHPL, p_giB,
        TT * NN, G3, HIDC);

    // ---- GRU chain: interleaved GEMM+gate mixed launches --------------------
    // L1(t) = { GEMM_F(t), gate_B(t-1) };  L2(t) = { GEMM_B(t), gate_F(t) }
    k_zero_h2<<<dim3((NN * GH + TB - 1) / TB, 2), TB>>>(p_hfs, p_hbs);
    for (int t = 0; t < TT; t++) {
        chain_step<<<NBGEMM + NBGATE, 256, GEMM_SMEM>>>(
            p_hfs, p_hfs + NN * GH, p_whhs_f, p_whhs_f + WHHPL, p_ghF,
            p_giB + (size_t)(TT - t) * NN * G3, p_ghB, bih_b, bhh_b, p_hbs,
            (t > 0) ? 1 : 0);
        chain_step<<<NBGEMM + NBGATE, 256, GEMM_SMEM>>>(
            p_hbs, p_hbs + NN * GH, p_whhs_b, p_whhs_b + WHHPL, p_ghB,
            p_giF + (size_t)t * NN * G3, p_ghF, bih_f, bhh_f, p_hfs, 1);
    }
    // final backward gate (t = TT-1 -> gi index 0)
    gate_one<<<NBGATE, 256>>>(p_giB, p_ghB, bih_b, bhh_b, p_hbs);

    // ---- mean + FC ----
    k_colmean<<<2 * GH, 256>>>(p_hfs, p_hbs, p_mean);
    k_fc<<<33, 128>>>(fc_w, fc_b, p_mean, out);
}